// round 16
// baseline (speedup 1.0000x reference)
#include <cuda_runtime.h>
#include <cuda_fp16.h>
#include <mma.h>

using namespace nvcuda;

#define NN   100000
#define FEAT 256
#define HID  128
#define OUTD 64
#define NE   3200000
#define SCB  1024
#define NBLK ((NN + SCB - 1) / SCB)   // 98

// ---------------- scratch (static device memory; no allocations) ----------------
__device__ __half g_xs[(size_t)NN * HID];
__device__ __half g_xt[(size_t)NN * HID];
__device__ __half g_cs[(size_t)NN * HID];
__device__ __half g_ct[(size_t)NN * HID];
__device__ float  g_fs[(size_t)NN * HID];
__device__ float  g_ft[(size_t)NN * HID];
__device__ int    g_rp [NN + 1];
__device__ int    g_rpT[NN + 1];
__device__ int    g_off [NN];
__device__ int    g_offT[NN];
__device__ int    g_part[2][128];
__device__ int2   g_ep [NE];    // packed (col, weight-bits)
__device__ int2   g_epT[NE];

// ---------------- CSR build ----------------
__global__ void zero_deg_kernel() {
    int i = blockIdx.x * blockDim.x + threadIdx.x;
    if (i < NN) { g_off[i] = 0; g_offT[i] = 0; }
}

__global__ void hist_kernel(const int* __restrict__ row, const int* __restrict__ col, int E) {
    int e = blockIdx.x * blockDim.x + threadIdx.x;
    if (e < E) {
        atomicAdd(&g_off [row[e]], 1);
        atomicAdd(&g_offT[col[e]], 1);
    }
}

// phase 1: per-block sums of both degree arrays
__global__ __launch_bounds__(SCB) void scan_partial_kernel() {
    int arr = blockIdx.y;
    const int* deg = arr ? g_offT : g_off;
    int i = blockIdx.x * SCB + threadIdx.x;
    int v = (i < NN) ? deg[i] : 0;
    __shared__ int sh[SCB];
    sh[threadIdx.x] = v;
    __syncthreads();
    for (int off = SCB / 2; off > 0; off >>= 1) {
        if (threadIdx.x < off) sh[threadIdx.x] += sh[threadIdx.x + off];
        __syncthreads();
    }
    if (threadIdx.x == 0) g_part[arr][blockIdx.x] = sh[0];
}

// phase 2 (fused): per-block prefix of partials + per-block exclusive scan -> row_ptr, cursors
__global__ __launch_bounds__(SCB) void scan_final_kernel(int E) {
    int arr = blockIdx.y;
    int* deg = arr ? g_offT : g_off;
    int* rp  = arr ? g_rpT  : g_rp;
    __shared__ int sh[SCB];
    __shared__ int base_sh;
    int i = blockIdx.x * SCB + threadIdx.x;
    int v = (i < NN) ? deg[i] : 0;
    if (threadIdx.x < 32) {
        int lane = threadIdx.x;
        int sum = 0;
        for (int j = lane; j < blockIdx.x; j += 32) sum += g_part[arr][j];
#pragma unroll
        for (int off = 16; off > 0; off >>= 1) sum += __shfl_down_sync(0xffffffffu, sum, off);
        if (lane == 0) base_sh = sum;
    }
    sh[threadIdx.x] = v;
    __syncthreads();
    for (int off = 1; off < SCB; off <<= 1) {
        int x = (threadIdx.x >= off) ? sh[threadIdx.x - off] : 0;
        __syncthreads();
        sh[threadIdx.x] += x;
        __syncthreads();
    }
    int excl = sh[threadIdx.x] - v + base_sh;
    if (i < NN) { rp[i] = excl; deg[i] = excl; }
    if (blockIdx.x == 0 && threadIdx.x == 0) rp[NN] = E;
}

__global__ void scatter_kernel(const int* __restrict__ row, const int* __restrict__ col,
                               const float* __restrict__ w, int E) {
    int e = blockIdx.x * blockDim.x + threadIdx.x;
    if (e < E) {
        int r = row[e], c = col[e];
        int wb = __float_as_int(w[e]);
        int p = atomicAdd(&g_off[r], 1);
        g_ep[p] = make_int2(c, wb);
        int q = atomicAdd(&g_offT[c], 1);
        g_epT[q] = make_int2(r, wb);
    }
}

// ---------------- helpers: fp32 -> (hi, lo) fp16 split ----------------
__device__ __forceinline__ void split_half(float v, __half& hi, __half& lo) {
    hi = __float2half_rn(v);
    lo = __float2half_rn(v - __half2float(hi));
}

// ---------------- input GEMMs (tensor, split-3 fp16): x = A @ W + b ----------------
// BM=64, BN=128, BK=32; 256 threads = 8 warps (2x4), each warp 32x32 (2x2 wmma frags)
struct GInShared {
    union {
        struct {
            __half Ahi[64][40];
            __half Alo[64][40];
            __half Whi[32][136];
            __half Wlo[32][136];
        } ld;
        float Csm[64][132];
    } u;
};

__global__ __launch_bounds__(256) void gemm_in_tc_kernel(
    const float* __restrict__ A0, const float* __restrict__ A1,
    const float* __restrict__ W0, const float* __restrict__ b0,
    const float* __restrict__ W1, const float* __restrict__ b1,
    const float* __restrict__ ws, const float* __restrict__ wt)
{
    const float* A; const float* W; const float* b;
    __half* X; float* F; float w0;
    if (blockIdx.y == 0) { A = A0; W = W0; b = b0; X = g_xs; F = g_fs; w0 = ws[0]; }
    else                 { A = A1; W = W1; b = b1; X = g_xt; F = g_ft; w0 = wt[0]; }

    __shared__ GInShared sh;
    int tid = threadIdx.x;
    int warp = tid >> 5;
    int wm = warp >> 2;          // 0..1
    int wn = warp & 3;           // 0..3
    int row0 = blockIdx.x * 64;

    wmma::fragment<wmma::accumulator, 16, 16, 16, float> c[2][2];
#pragma unroll
    for (int i = 0; i < 2; i++)
#pragma unroll
        for (int j = 0; j < 2; j++) wmma::fill_fragment(c[i][j], 0.f);

    for (int kt = 0; kt < FEAT; kt += 32) {
#pragma unroll
        for (int t = 0; t < 2; t++) {
            int idx = tid + t * 256;
            int r = idx >> 3;            // 0..63
            int kq = (idx & 7) * 4;      // 0,4,..,28
            float4 av = make_float4(0.f, 0.f, 0.f, 0.f);
            int grow = row0 + r;
            if (grow < NN) av = *(const float4*)(A + (size_t)grow * FEAT + kt + kq);
            __half hi, lo;
            split_half(av.x, hi, lo); sh.u.ld.Ahi[r][kq + 0] = hi; sh.u.ld.Alo[r][kq + 0] = lo;
            split_half(av.y, hi, lo); sh.u.ld.Ahi[r][kq + 1] = hi; sh.u.ld.Alo[r][kq + 1] = lo;
            split_half(av.z, hi, lo); sh.u.ld.Ahi[r][kq + 2] = hi; sh.u.ld.Alo[r][kq + 2] = lo;
            split_half(av.w, hi, lo); sh.u.ld.Ahi[r][kq + 3] = hi; sh.u.ld.Alo[r][kq + 3] = lo;
        }
#pragma unroll
        for (int t = 0; t < 4; t++) {
            int idx = tid + t * 256;
            int r = idx >> 5;            // 0..31
            int nq = (idx & 31) * 4;     // 0..124
            float4 wv = *(const float4*)(W + (size_t)(kt + r) * HID + nq);
            __half hi, lo;
            split_half(wv.x, hi, lo); sh.u.ld.Whi[r][nq + 0] = hi; sh.u.ld.Wlo[r][nq + 0] = lo;
            split_half(wv.y, hi, lo); sh.u.ld.Whi[r][nq + 1] = hi; sh.u.ld.Wlo[r][nq + 1] = lo;
            split_half(wv.z, hi, lo); sh.u.ld.Whi[r][nq + 2] = hi; sh.u.ld.Wlo[r][nq + 2] = lo;
            split_half(wv.w, hi, lo); sh.u.ld.Whi[r][nq + 3] = hi; sh.u.ld.Wlo[r][nq + 3] = lo;
        }
        __syncthreads();

#pragma unroll
        for (int kk = 0; kk < 32; kk += 16) {
            wmma::fragment<wmma::matrix_a, 16, 16, 16, __half, wmma::row_major> ahi[2], alo[2];
            wmma::fragment<wmma::matrix_b, 16, 16, 16, __half, wmma::row_major> bhi[2], blo[2];
#pragma unroll
            for (int i = 0; i < 2; i++) {
                wmma::load_matrix_sync(ahi[i], &sh.u.ld.Ahi[wm * 32 + i * 16][kk], 40);
                wmma::load_matrix_sync(alo[i], &sh.u.ld.Alo[wm * 32 + i * 16][kk], 40);
            }
#pragma unroll
            for (int j = 0; j < 2; j++) {
                wmma::load_matrix_sync(bhi[j], &sh.u.ld.Whi[kk][wn * 32 + j * 16], 136);
                wmma::load_matrix_sync(blo[j], &sh.u.ld.Wlo[kk][wn * 32 + j * 16], 136);
            }
#pragma unroll
            for (int i = 0; i < 2; i++)
#pragma unroll
                for (int j = 0; j < 2; j++) {
                    wmma::mma_sync(c[i][j], ahi[i], bhi[j], c[i][j]);
                    wmma::mma_sync(c[i][j], alo[i], bhi[j], c[i][j]);
                    wmma::mma_sync(c[i][j], ahi[i], blo[j], c[i][j]);
                }
        }
        __syncthreads();
    }

#pragma unroll
    for (int i = 0; i < 2; i++)
#pragma unroll
        for (int j = 0; j < 2; j++)
            wmma::store_matrix_sync(&sh.u.Csm[wm * 32 + i * 16][wn * 32 + j * 16],
                                    c[i][j], 132, wmma::mem_row_major);
    __syncthreads();

    int tx = tid & 31;           // col group of 4
    int ty = tid >> 5;           // 8 row groups of 8
    float bb[4];
#pragma unroll
    for (int j = 0; j < 4; j++) bb[j] = b[tx * 4 + j];
#pragma unroll
    for (int i = 0; i < 8; i++) {
        int r = ty * 8 + i;
        int row = row0 + r;
        if (row < NN) {
            float4 xv;
            xv.x = sh.u.Csm[r][tx * 4 + 0] + bb[0];
            xv.y = sh.u.Csm[r][tx * 4 + 1] + bb[1];
            xv.z = sh.u.Csm[r][tx * 4 + 2] + bb[2];
            xv.w = sh.u.Csm[r][tx * 4 + 3] + bb[3];
            float4 fv;
            fv.x = w0 * xv.x; fv.y = w0 * xv.y; fv.z = w0 * xv.z; fv.w = w0 * xv.w;
            __half2 h0 = __floats2half2_rn(xv.x, xv.y);
            __half2 h1 = __floats2half2_rn(xv.z, xv.w);
            uint2 u; u.x = *(unsigned*)&h0; u.y = *(unsigned*)&h1;
            *(uint2*)(X + (size_t)row * HID + tx * 4) = u;
            *(float4*)(F + (size_t)row * HID + tx * 4) = fv;
        }
    }
}

// ---------------- CSR gather SPMM (half in/out, fp32 accum + feat RMW, 2-wide pipelined) ----------------
// blockIdx.y: 0 = source path (adj), 1 = target path (adj^T). pp: ping-pong selector.
__global__ __launch_bounds__(256) void spmm_kernel(int pp, int hop,
                                                   const float* __restrict__ wsp,
                                                   const float* __restrict__ wtp)
{
    int which = blockIdx.y;
    int w = (blockIdx.x * blockDim.x + threadIdx.x) >> 5;
    int lane = threadIdx.x & 31;
    if (w >= NN) return;

    const int* rp; const int2* ep;
    const __half* xin; __half* xout; float* feat; float wh;
    if (which == 0) {
        rp = g_rp;  ep = g_ep;  feat = g_fs; wh = wsp[hop];
        xin  = pp ? g_cs : g_xs;
        xout = pp ? g_xs : g_cs;
    } else {
        rp = g_rpT; ep = g_epT; feat = g_ft; wh = wtp[hop];
        xin  = pp ? g_ct : g_xt;
        xout = pp ? g_xt : g_ct;
    }

    int s = rp[w], e = rp[w + 1];
    float a0x = 0.f, a0y = 0.f, a0z = 0.f, a0w = 0.f;
    float a1x = 0.f, a1y = 0.f, a1z = 0.f, a1w = 0.f;
    int i = s;
    for (; i + 1 < e; i += 2) {
        int2 p0 = __ldg(&ep[i]);
        int2 p1 = __ldg(&ep[i + 1]);
        uint2 u0 = __ldg((const uint2*)(xin + (size_t)p0.x * HID + lane * 4));
        uint2 u1 = __ldg((const uint2*)(xin + (size_t)p1.x * HID + lane * 4));
        float t0 = __int_as_float(p0.y);
        float t1 = __int_as_float(p1.y);
        float2 f00 = __half22float2(*(__half2*)&u0.x);
        float2 f01 = __half22float2(*(__half2*)&u0.y);
        float2 f10 = __half22float2(*(__half2*)&u1.x);
        float2 f11 = __half22float2(*(__half2*)&u1.y);
        a0x += t0 * f00.x; a0y += t0 * f00.y; a0z += t0 * f01.x; a0w += t0 * f01.y;
        a1x += t1 * f10.x; a1y += t1 * f10.y; a1z += t1 * f11.x; a1w += t1 * f11.y;
    }
    if (i < e) {
        int2 p0 = __ldg(&ep[i]);
        uint2 u0 = __ldg((const uint2*)(xin + (size_t)p0.x * HID + lane * 4));
        float t0 = __int_as_float(p0.y);
        float2 f00 = __half22float2(*(__half2*)&u0.x);
        float2 f01 = __half22float2(*(__half2*)&u0.y);
        a0x += t0 * f00.x; a0y += t0 * f00.y; a0z += t0 * f01.x; a0w += t0 * f01.y;
    }
    float ax = a0x + a1x, ay = a0y + a1y, az = a0z + a1z, aw = a0w + a1w;
    size_t o = (size_t)w * HID + lane * 4;
    __half2 o0 = __floats2half2_rn(ax, ay);
    __half2 o1 = __floats2half2_rn(az, aw);
    uint2 uo; uo.x = *(unsigned*)&o0; uo.y = *(unsigned*)&o1;
    *(uint2*)(xout + o) = uo;
    float4 f = *(float4*)(feat + o);
    f.x += wh * ax; f.y += wh * ay; f.z += wh * az; f.w += wh * aw;
    *(float4*)(feat + o) = f;
}

// ---------------- output GEMM (tensor, split-3): out = [fs | ft] @ W_node + b_node ----------------
// BM=64, BN=64, BK=32; 128 threads = 4 warps (2x2), each warp 32x32
struct GOutShared {
    union {
        struct {
            __half Ahi[64][40];
            __half Alo[64][40];
            __half Whi[32][72];
            __half Wlo[32][72];
        } ld;
        float Csm[64][68];
    } u;
};

__global__ __launch_bounds__(128) void gemm_out_tc_kernel(
    const float* __restrict__ Wn, const float* __restrict__ bn, float* __restrict__ out)
{
    __shared__ GOutShared sh;
    int tid = threadIdx.x;
    int warp = tid >> 5;
    int wm = warp >> 1;          // 0..1
    int wn = warp & 1;           // 0..1
    int row0 = blockIdx.x * 64;

    wmma::fragment<wmma::accumulator, 16, 16, 16, float> c[2][2];
#pragma unroll
    for (int i = 0; i < 2; i++)
#pragma unroll
        for (int j = 0; j < 2; j++) wmma::fill_fragment(c[i][j], 0.f);

    for (int kt = 0; kt < 2 * HID; kt += 32) {
        const float* Abase = (kt < HID) ? g_fs : g_ft;
        int kloc = (kt < HID) ? kt : kt - HID;
        // A tile 64x32 = 512 float4, 4 per thread
#pragma unroll
        for (int t = 0; t < 4; t++) {
            int idx = tid + t * 128;
            int r = idx >> 3;
            int kq = (idx & 7) * 4;
            float4 av = make_float4(0.f, 0.f, 0.f, 0.f);
            int grow = row0 + r;
            if (grow < NN) av = *(const float4*)(Abase + (size_t)grow * HID + kloc + kq);
            __half hi, lo;
            split_half(av.x, hi, lo); sh.u.ld.Ahi[r][kq + 0] = hi; sh.u.ld.Alo[r][kq + 0] = lo;
            split_half(av.y, hi, lo); sh.u.ld.Ahi[r][kq + 1] = hi; sh.u.ld.Alo[r][kq + 1] = lo;
            split_half(av.z, hi, lo); sh.u.ld.Ahi[r][kq + 2] = hi; sh.u.ld.Alo[r][kq + 2] = lo;
            split_half(av.w, hi, lo); sh.u.ld.Ahi[r][kq + 3] = hi; sh.u.ld.Alo[r][kq + 3] = lo;
        }
        // W tile 32x64 = 512 float4, 4 per thread
#pragma unroll
        for (int t = 0; t < 4; t++) {
            int idx = tid + t * 128;
            int r = idx >> 4;
            int nq = (idx & 15) * 4;
            float4 wv = *(const float4*)(Wn + (size_t)(kt + r) * OUTD + nq);
            __half hi, lo;
            split_half(wv.x, hi, lo); sh.u.ld.Whi[r][nq + 0] = hi; sh.u.ld.Wlo[r][nq + 0] = lo;
            split_half(wv.y, hi, lo); sh.u.ld.Whi[r][nq + 1] = hi; sh.u.ld.Wlo[r][nq + 1] = lo;
            split_half(wv.z, hi, lo); sh.u.ld.Whi[r][nq + 2] = hi; sh.u.ld.Wlo[r][nq + 2] = lo;
            split_half(wv.w, hi, lo); sh.u.ld.Whi[r][nq + 3] = hi; sh.u.ld.Wlo[r][nq + 3] = lo;
        }
        __syncthreads();

#pragma unroll
        for (int kk = 0; kk < 32; kk += 16) {
            wmma::fragment<wmma::matrix_a, 16, 16, 16, __half, wmma::row_major> ahi[2], alo[2];
            wmma::fragment<wmma::matrix_b, 16, 16, 16, __half, wmma::row_major> bhi[2], blo[2];
#pragma unroll
            for (int i = 0; i < 2; i++) {
                wmma::load_matrix_sync(ahi[i], &sh.u.ld.Ahi[wm * 32 + i * 16][kk], 40);
                wmma::load_matrix_sync(alo[i], &sh.u.ld.Alo[wm * 32 + i * 16][kk], 40);
            }
#pragma unroll
            for (int j = 0; j < 2; j++) {
                wmma::load_matrix_sync(bhi[j], &sh.u.ld.Whi[kk][wn * 32 + j * 16], 72);
                wmma::load_matrix_sync(blo[j], &sh.u.ld.Wlo[kk][wn * 32 + j * 16], 72);
            }
#pragma unroll
            for (int i = 0; i < 2; i++)
#pragma unroll
                for (int j = 0; j < 2; j++) {
                    wmma::mma_sync(c[i][j], ahi[i], bhi[j], c[i][j]);
                    wmma::mma_sync(c[i][j], alo[i], bhi[j], c[i][j]);
                    wmma::mma_sync(c[i][j], ahi[i], blo[j], c[i][j]);
                }
        }
        __syncthreads();
    }

#pragma unroll
    for (int i = 0; i < 2; i++)
#pragma unroll
        for (int j = 0; j < 2; j++)
            wmma::store_matrix_sync(&sh.u.Csm[wm * 32 + i * 16][wn * 32 + j * 16],
                                    c[i][j], 68, wmma::mem_row_major);
    __syncthreads();

    int tx = tid & 15;           // 16 col groups of 4
    int ty = tid >> 4;           // 8 row groups of 8
    float bb[4];
#pragma unroll
    for (int j = 0; j < 4; j++) bb[j] = bn[tx * 4 + j];
#pragma unroll
    for (int i = 0; i < 8; i++) {
        int r = ty * 8 + i;
        int row = row0 + r;
        if (row < NN) {
            float4 ov;
            ov.x = sh.u.Csm[r][tx * 4 + 0] + bb[0];
            ov.y = sh.u.Csm[r][tx * 4 + 1] + bb[1];
            ov.z = sh.u.Csm[r][tx * 4 + 2] + bb[2];
            ov.w = sh.u.Csm[r][tx * 4 + 3] + bb[3];
            *(float4*)(out + (size_t)row * OUTD + tx * 4) = ov;
        }
    }
}

// ---------------- launch ----------------
extern "C" void kernel_launch(void* const* d_in, const int* in_sizes, int n_in,
                              void* d_out, int out_size)
{
    const float* fsrc  = (const float*)d_in[0];
    const float* ftgt  = (const float*)d_in[1];
    const int*   erow  = (const int*)d_in[2];
    const int*   ecol  = (const int*)d_in[3];
    const float* ew    = (const float*)d_in[4];
    const float* Wsrc  = (const float*)d_in[5];
    const float* bsrc  = (const float*)d_in[6];
    const float* Wtgt  = (const float*)d_in[7];
    const float* btgt  = (const float*)d_in[8];
    const float* ws    = (const float*)d_in[9];
    const float* wt    = (const float*)d_in[10];
    const float* Wnode = (const float*)d_in[11];
    const float* bnode = (const float*)d_in[12];
    float* out = (float*)d_out;
    int E = in_sizes[2];
    if (E > NE) E = NE;

    zero_deg_kernel<<<(NN + 255) / 256, 256>>>();

    dim3 gg((NN + 63) / 64, 2);
    gemm_in_tc_kernel<<<gg, 256>>>(fsrc, ftgt, Wsrc, bsrc, Wtgt, btgt, ws, wt);

    int eg = (E + 255) / 256;
    hist_kernel<<<eg, 256>>>(erow, ecol, E);
    dim3 sgr(NBLK, 2);
    scan_partial_kernel<<<sgr, SCB>>>();
    scan_final_kernel<<<sgr, SCB>>>(E);
    scatter_kernel<<<eg, 256>>>(erow, ecol, ew, E);

    dim3 sg((NN * 32 + 255) / 256, 2);  // one warp per row, y = path
    spmm_kernel<<<sg, 256>>>(0, 1, ws, wt);  // hop 1: x -> c
    spmm_kernel<<<sg, 256>>>(1, 2, ws, wt);  // hop 2: c -> x
    spmm_kernel<<<sg, 256>>>(0, 3, ws, wt);  // hop 3: x -> c

    gemm_out_tc_kernel<<<(NN + 63) / 64, 128>>>(Wnode, bnode, out);
}

// round 17
// speedup vs baseline: 1.3023x; 1.3023x over previous
#include <cuda_runtime.h>
#include <cuda_fp16.h>
#include <mma.h>

using namespace nvcuda;

#define NN   100000
#define FEAT 256
#define HID  128
#define OUTD 64
#define NE   3200000
#define SCB  1024
#define NBLK ((NN + SCB - 1) / SCB)   // 98

// ---------------- scratch (static device memory; no allocations) ----------------
__device__ __half g_xs [(size_t)NN * HID];
__device__ __half g_xt [(size_t)NN * HID];
__device__ __half g_h1s[(size_t)NN * HID];
__device__ __half g_h1t[(size_t)NN * HID];
__device__ __half g_h2s[(size_t)NN * HID];
__device__ __half g_h2t[(size_t)NN * HID];
__device__ __half g_h3s[(size_t)NN * HID];
__device__ __half g_h3t[(size_t)NN * HID];
__device__ int    g_rp [NN + 1];
__device__ int    g_rpT[NN + 1];
__device__ int    g_off [NN];
__device__ int    g_offT[NN];
__device__ int    g_part[2][128];
__device__ int2   g_ep [NE];    // packed (col, weight-bits)
__device__ int2   g_epT[NE];

// ---------------- CSR build ----------------
__global__ void zero_deg_kernel() {
    int i = blockIdx.x * blockDim.x + threadIdx.x;
    if (i < NN) { g_off[i] = 0; g_offT[i] = 0; }
}

__global__ void hist_kernel(const int* __restrict__ row, const int* __restrict__ col, int E) {
    int e = blockIdx.x * blockDim.x + threadIdx.x;
    if (e < E) {
        atomicAdd(&g_off [row[e]], 1);
        atomicAdd(&g_offT[col[e]], 1);
    }
}

// phase 1: per-block sums of both degree arrays
__global__ __launch_bounds__(SCB) void scan_partial_kernel() {
    int arr = blockIdx.y;
    const int* deg = arr ? g_offT : g_off;
    int i = blockIdx.x * SCB + threadIdx.x;
    int v = (i < NN) ? deg[i] : 0;
    __shared__ int sh[SCB];
    sh[threadIdx.x] = v;
    __syncthreads();
    for (int off = SCB / 2; off > 0; off >>= 1) {
        if (threadIdx.x < off) sh[threadIdx.x] += sh[threadIdx.x + off];
        __syncthreads();
    }
    if (threadIdx.x == 0) g_part[arr][blockIdx.x] = sh[0];
}

// phase 2 (fused): per-block prefix of partials + per-block exclusive scan -> row_ptr, cursors
__global__ __launch_bounds__(SCB) void scan_final_kernel(int E) {
    int arr = blockIdx.y;
    int* deg = arr ? g_offT : g_off;
    int* rp  = arr ? g_rpT  : g_rp;
    __shared__ int sh[SCB];
    __shared__ int base_sh;
    int i = blockIdx.x * SCB + threadIdx.x;
    int v = (i < NN) ? deg[i] : 0;
    if (threadIdx.x < 32) {
        int lane = threadIdx.x;
        int sum = 0;
        for (int j = lane; j < blockIdx.x; j += 32) sum += g_part[arr][j];
#pragma unroll
        for (int off = 16; off > 0; off >>= 1) sum += __shfl_down_sync(0xffffffffu, sum, off);
        if (lane == 0) base_sh = sum;
    }
    sh[threadIdx.x] = v;
    __syncthreads();
    for (int off = 1; off < SCB; off <<= 1) {
        int x = (threadIdx.x >= off) ? sh[threadIdx.x - off] : 0;
        __syncthreads();
        sh[threadIdx.x] += x;
        __syncthreads();
    }
    int excl = sh[threadIdx.x] - v + base_sh;
    if (i < NN) { rp[i] = excl; deg[i] = excl; }
    if (blockIdx.x == 0 && threadIdx.x == 0) rp[NN] = E;
}

__global__ void scatter_kernel(const int* __restrict__ row, const int* __restrict__ col,
                               const float* __restrict__ w, int E) {
    int e = blockIdx.x * blockDim.x + threadIdx.x;
    if (e < E) {
        int r = row[e], c = col[e];
        int wb = __float_as_int(w[e]);
        int p = atomicAdd(&g_off[r], 1);
        g_ep[p] = make_int2(c, wb);
        int q = atomicAdd(&g_offT[c], 1);
        g_epT[q] = make_int2(r, wb);
    }
}

// ---------------- helpers: fp32 -> (hi, lo) fp16 split ----------------
__device__ __forceinline__ void split_half(float v, __half& hi, __half& lo) {
    hi = __float2half_rn(v);
    lo = __float2half_rn(v - __half2float(hi));
}

// ---------------- input GEMMs (tensor, split-3 fp16): x = A @ W + b -> fp16 ----------------
// BM=64, BN=128, BK=32; 256 threads = 8 warps (2x4), each warp 32x32 (2x2 wmma frags)
struct GInShared {
    union {
        struct {
            __half Ahi[64][40];
            __half Alo[64][40];
            __half Whi[32][136];
            __half Wlo[32][136];
        } ld;
        float Csm[64][132];
    } u;
};

__global__ __launch_bounds__(256) void gemm_in_tc_kernel(
    const float* __restrict__ A0, const float* __restrict__ A1,
    const float* __restrict__ W0, const float* __restrict__ b0,
    const float* __restrict__ W1, const float* __restrict__ b1)
{
    const float* A; const float* W; const float* b; __half* X;
    if (blockIdx.y == 0) { A = A0; W = W0; b = b0; X = g_xs; }
    else                 { A = A1; W = W1; b = b1; X = g_xt; }

    __shared__ GInShared sh;
    int tid = threadIdx.x;
    int warp = tid >> 5;
    int wm = warp >> 2;          // 0..1
    int wn = warp & 3;           // 0..3
    int row0 = blockIdx.x * 64;

    wmma::fragment<wmma::accumulator, 16, 16, 16, float> c[2][2];
#pragma unroll
    for (int i = 0; i < 2; i++)
#pragma unroll
        for (int j = 0; j < 2; j++) wmma::fill_fragment(c[i][j], 0.f);

    for (int kt = 0; kt < FEAT; kt += 32) {
#pragma unroll
        for (int t = 0; t < 2; t++) {
            int idx = tid + t * 256;
            int r = idx >> 3;
            int kq = (idx & 7) * 4;
            float4 av = make_float4(0.f, 0.f, 0.f, 0.f);
            int grow = row0 + r;
            if (grow < NN) av = *(const float4*)(A + (size_t)grow * FEAT + kt + kq);
            __half hi, lo;
            split_half(av.x, hi, lo); sh.u.ld.Ahi[r][kq + 0] = hi; sh.u.ld.Alo[r][kq + 0] = lo;
            split_half(av.y, hi, lo); sh.u.ld.Ahi[r][kq + 1] = hi; sh.u.ld.Alo[r][kq + 1] = lo;
            split_half(av.z, hi, lo); sh.u.ld.Ahi[r][kq + 2] = hi; sh.u.ld.Alo[r][kq + 2] = lo;
            split_half(av.w, hi, lo); sh.u.ld.Ahi[r][kq + 3] = hi; sh.u.ld.Alo[r][kq + 3] = lo;
        }
#pragma unroll
        for (int t = 0; t < 4; t++) {
            int idx = tid + t * 256;
            int r = idx >> 5;
            int nq = (idx & 31) * 4;
            float4 wv = *(const float4*)(W + (size_t)(kt + r) * HID + nq);
            __half hi, lo;
            split_half(wv.x, hi, lo); sh.u.ld.Whi[r][nq + 0] = hi; sh.u.ld.Wlo[r][nq + 0] = lo;
            split_half(wv.y, hi, lo); sh.u.ld.Whi[r][nq + 1] = hi; sh.u.ld.Wlo[r][nq + 1] = lo;
            split_half(wv.z, hi, lo); sh.u.ld.Whi[r][nq + 2] = hi; sh.u.ld.Wlo[r][nq + 2] = lo;
            split_half(wv.w, hi, lo); sh.u.ld.Whi[r][nq + 3] = hi; sh.u.ld.Wlo[r][nq + 3] = lo;
        }
        __syncthreads();

#pragma unroll
        for (int kk = 0; kk < 32; kk += 16) {
            wmma::fragment<wmma::matrix_a, 16, 16, 16, __half, wmma::row_major> ahi[2], alo[2];
            wmma::fragment<wmma::matrix_b, 16, 16, 16, __half, wmma::row_major> bhi[2], blo[2];
#pragma unroll
            for (int i = 0; i < 2; i++) {
                wmma::load_matrix_sync(ahi[i], &sh.u.ld.Ahi[wm * 32 + i * 16][kk], 40);
                wmma::load_matrix_sync(alo[i], &sh.u.ld.Alo[wm * 32 + i * 16][kk], 40);
            }
#pragma unroll
            for (int j = 0; j < 2; j++) {
                wmma::load_matrix_sync(bhi[j], &sh.u.ld.Whi[kk][wn * 32 + j * 16], 136);
                wmma::load_matrix_sync(blo[j], &sh.u.ld.Wlo[kk][wn * 32 + j * 16], 136);
            }
#pragma unroll
            for (int i = 0; i < 2; i++)
#pragma unroll
                for (int j = 0; j < 2; j++) {
                    wmma::mma_sync(c[i][j], ahi[i], bhi[j], c[i][j]);
                    wmma::mma_sync(c[i][j], alo[i], bhi[j], c[i][j]);
                    wmma::mma_sync(c[i][j], ahi[i], blo[j], c[i][j]);
                }
        }
        __syncthreads();
    }

#pragma unroll
    for (int i = 0; i < 2; i++)
#pragma unroll
        for (int j = 0; j < 2; j++)
            wmma::store_matrix_sync(&sh.u.Csm[wm * 32 + i * 16][wn * 32 + j * 16],
                                    c[i][j], 132, wmma::mem_row_major);
    __syncthreads();

    int tx = tid & 31;
    int ty = tid >> 5;
    float bb[4];
#pragma unroll
    for (int j = 0; j < 4; j++) bb[j] = b[tx * 4 + j];
#pragma unroll
    for (int i = 0; i < 8; i++) {
        int r = ty * 8 + i;
        int row = row0 + r;
        if (row < NN) {
            float4 xv;
            xv.x = sh.u.Csm[r][tx * 4 + 0] + bb[0];
            xv.y = sh.u.Csm[r][tx * 4 + 1] + bb[1];
            xv.z = sh.u.Csm[r][tx * 4 + 2] + bb[2];
            xv.w = sh.u.Csm[r][tx * 4 + 3] + bb[3];
            __half2 h0 = __floats2half2_rn(xv.x, xv.y);
            __half2 h1 = __floats2half2_rn(xv.z, xv.w);
            uint2 u; u.x = *(unsigned*)&h0; u.y = *(unsigned*)&h1;
            *(uint2*)(X + (size_t)row * HID + tx * 4) = u;
        }
    }
}

// ---------------- CSR gather SPMM (half in/out, fp32 accum, serial loop) ----------------
// blockIdx.y: 0 = source path (adj), 1 = target path (adj^T). hop selects buffers.
__global__ __launch_bounds__(256) void spmm_kernel(int hop)
{
    int which = blockIdx.y;
    int w = (blockIdx.x * blockDim.x + threadIdx.x) >> 5;
    int lane = threadIdx.x & 31;
    if (w >= NN) return;

    const int*  rp = which ? g_rpT : g_rp;
    const int2* ep = which ? g_epT : g_ep;
    const __half* xin; __half* xout;
    if (hop == 1)      { xin = which ? g_xt  : g_xs;  xout = which ? g_h1t : g_h1s; }
    else if (hop == 2) { xin = which ? g_h1t : g_h1s; xout = which ? g_h2t : g_h2s; }
    else               { xin = which ? g_h2t : g_h2s; xout = which ? g_h3t : g_h3s; }

    int s = rp[w], e = rp[w + 1];
    float ax = 0.f, ay = 0.f, az = 0.f, aw = 0.f;
    for (int i = s; i < e; i++) {
        int2 pr = __ldg(&ep[i]);
        int   c = pr.x;
        float t = __int_as_float(pr.y);
        uint2 u = __ldg((const uint2*)(xin + (size_t)c * HID + lane * 4));
        __half2 h0 = *(__half2*)&u.x;
        __half2 h1 = *(__half2*)&u.y;
        float2 f0 = __half22float2(h0);
        float2 f1 = __half22float2(h1);
        ax += t * f0.x; ay += t * f0.y; az += t * f1.x; aw += t * f1.y;
    }
    __half2 o0 = __floats2half2_rn(ax, ay);
    __half2 o1 = __floats2half2_rn(az, aw);
    uint2 uo; uo.x = *(unsigned*)&o0; uo.y = *(unsigned*)&o1;
    *(uint2*)(xout + (size_t)w * HID + lane * 4) = uo;
}

// ---------------- output GEMM (tensor, split-3): out = [Σ ws_h hs_h | Σ wt_h ht_h] @ W_node + b ----------------
// BM=64, BN=64, BK=32; 128 threads = 4 warps (2x2), each warp 32x32
struct GOutShared {
    union {
        struct {
            __half Ahi[64][40];
            __half Alo[64][40];
            __half Whi[32][72];
            __half Wlo[32][72];
        } ld;
        float Csm[64][68];
    } u;
};

__global__ __launch_bounds__(128) void gemm_out_tc_kernel(
    const float* __restrict__ Wn, const float* __restrict__ bn,
    const float* __restrict__ wsv, const float* __restrict__ wtv,
    float* __restrict__ out)
{
    __shared__ GOutShared sh;
    int tid = threadIdx.x;
    int warp = tid >> 5;
    int wm = warp >> 1;
    int wn = warp & 1;
    int row0 = blockIdx.x * 64;

    float ws0 = __ldg(&wsv[0]), ws1 = __ldg(&wsv[1]), ws2 = __ldg(&wsv[2]), ws3 = __ldg(&wsv[3]);
    float wt0 = __ldg(&wtv[0]), wt1 = __ldg(&wtv[1]), wt2 = __ldg(&wtv[2]), wt3 = __ldg(&wtv[3]);

    wmma::fragment<wmma::accumulator, 16, 16, 16, float> c[2][2];
#pragma unroll
    for (int i = 0; i < 2; i++)
#pragma unroll
        for (int j = 0; j < 2; j++) wmma::fill_fragment(c[i][j], 0.f);

    for (int kt = 0; kt < 2 * HID; kt += 32) {
        bool is_s = (kt < HID);
        int kloc = is_s ? kt : kt - HID;
        const __half* p0 = is_s ? g_xs  : g_xt;
        const __half* p1 = is_s ? g_h1s : g_h1t;
        const __half* p2 = is_s ? g_h2s : g_h2t;
        const __half* p3 = is_s ? g_h3s : g_h3t;
        float c0 = is_s ? ws0 : wt0, c1 = is_s ? ws1 : wt1;
        float c2 = is_s ? ws2 : wt2, c3 = is_s ? ws3 : wt3;

        // A tile 64x32: weighted combine of 4 fp16 arrays -> split hi/lo
#pragma unroll
        for (int t = 0; t < 4; t++) {
            int idx = tid + t * 128;
            int r = idx >> 3;
            int kq = (idx & 7) * 4;
            int grow = row0 + r;
            float v[4] = {0.f, 0.f, 0.f, 0.f};
            if (grow < NN) {
                size_t off = (size_t)grow * HID + kloc + kq;
                uint2 q0 = __ldg((const uint2*)(p0 + off));
                uint2 q1 = __ldg((const uint2*)(p1 + off));
                uint2 q2 = __ldg((const uint2*)(p2 + off));
                uint2 q3 = __ldg((const uint2*)(p3 + off));
                float2 a0 = __half22float2(*(__half2*)&q0.x), a1 = __half22float2(*(__half2*)&q0.y);
                float2 b0 = __half22float2(*(__half2*)&q1.x), b1 = __half22float2(*(__half2*)&q1.y);
                float2 d0 = __half22float2(*(__half2*)&q2.x), d1 = __half22float2(*(__half2*)&q2.y);
                float2 e0 = __half22float2(*(__half2*)&q3.x), e1 = __half22float2(*(__half2*)&q3.y);
                v[0] = c0 * a0.x + c1 * b0.x + c2 * d0.x + c3 * e0.x;
                v[1] = c0 * a0.y + c1 * b0.y + c2 * d0.y + c3 * e0.y;
                v[2] = c0 * a1.x + c1 * b1.x + c2 * d1.x + c3 * e1.x;
                v[3] = c0 * a1.y + c1 * b1.y + c2 * d1.y + c3 * e1.y;
            }
#pragma unroll
            for (int q = 0; q < 4; q++) {
                __half hi, lo;
                split_half(v[q], hi, lo);
                sh.u.ld.Ahi[r][kq + q] = hi;
                sh.u.ld.Alo[r][kq + q] = lo;
            }
        }
        // W tile 32x64 = 512 float4, 4 per thread
#pragma unroll
        for (int t = 0; t < 4; t++) {
            int idx = tid + t * 128;
            int r = idx >> 4;
            int nq = (idx & 15) * 4;
            float4 wv = *(const float4*)(Wn + (size_t)(kt + r) * OUTD + nq);
            __half hi, lo;
            split_half(wv.x, hi, lo); sh.u.ld.Whi[r][nq + 0] = hi; sh.u.ld.Wlo[r][nq + 0] = lo;
            split_half(wv.y, hi, lo); sh.u.ld.Whi[r][nq + 1] = hi; sh.u.ld.Wlo[r][nq + 1] = lo;
            split_half(wv.z, hi, lo); sh.u.ld.Whi[r][nq + 2] = hi; sh.u.ld.Wlo[r][nq + 2] = lo;
            split_half(wv.w, hi, lo); sh.u.ld.Whi[r][nq + 3] = hi; sh.u.ld.Wlo[r][nq + 3] = lo;
        }
        __syncthreads();

#pragma unroll
        for (int kk = 0; kk < 32; kk += 16) {
            wmma::fragment<wmma::matrix_a, 16, 16, 16, __half, wmma::row_major> ahi[2], alo[2];
            wmma::fragment<wmma::matrix_b, 16, 16, 16, __half, wmma::row_major> bhi[2], blo[2];
#pragma unroll
            for (int i = 0; i < 2; i++) {
                wmma::load_matrix_sync(ahi[i], &sh.u.ld.Ahi[wm * 32 + i * 16][kk], 40);
                wmma::load_matrix_sync(alo[i], &sh.u.ld.Alo[wm * 32 + i * 16][kk], 40);
            }
#pragma unroll
            for (int j = 0; j < 2; j++) {
                wmma::load_matrix_sync(bhi[j], &sh.u.ld.Whi[kk][wn * 32 + j * 16], 72);
                wmma::load_matrix_sync(blo[j], &sh.u.ld.Wlo[kk][wn * 32 + j * 16], 72);
            }
#pragma unroll
            for (int i = 0; i < 2; i++)
#pragma unroll
                for (int j = 0; j < 2; j++) {
                    wmma::mma_sync(c[i][j], ahi[i], bhi[j], c[i][j]);
                    wmma::mma_sync(c[i][j], alo[i], bhi[j], c[i][j]);
                    wmma::mma_sync(c[i][j], ahi[i], blo[j], c[i][j]);
                }
        }
        __syncthreads();
    }

#pragma unroll
    for (int i = 0; i < 2; i++)
#pragma unroll
        for (int j = 0; j < 2; j++)
            wmma::store_matrix_sync(&sh.u.Csm[wm * 32 + i * 16][wn * 32 + j * 16],
                                    c[i][j], 68, wmma::mem_row_major);
    __syncthreads();

    int tx = tid & 15;
    int ty = tid >> 4;
    float bb[4];
#pragma unroll
    for (int j = 0; j < 4; j++) bb[j] = bn[tx * 4 + j];
#pragma unroll
    for (int i = 0; i < 8; i++) {
        int r = ty * 8 + i;
        int row = row0 + r;
        if (row < NN) {
            float4 ov;
            ov.x = sh.u.Csm[r][tx * 4 + 0] + bb[0];
            ov.y = sh.u.Csm[r][tx * 4 + 1] + bb[1];
            ov.z = sh.u.Csm[r][tx * 4 + 2] + bb[2];
            ov.w = sh.u.Csm[r][tx * 4 + 3] + bb[3];
            *(float4*)(out + (size_t)row * OUTD + tx * 4) = ov;
        }
    }
}

// ---------------- launch ----------------
extern "C" void kernel_launch(void* const* d_in, const int* in_sizes, int n_in,
                              void* d_out, int out_size)
{
    const float* fsrc  = (const float*)d_in[0];
    const float* ftgt  = (const float*)d_in[1];
    const int*   erow  = (const int*)d_in[2];
    const int*   ecol  = (const int*)d_in[3];
    const float* ew    = (const float*)d_in[4];
    const float* Wsrc  = (const float*)d_in[5];
    const float* bsrc  = (const float*)d_in[6];
    const float* Wtgt  = (const float*)d_in[7];
    const float* btgt  = (const float*)d_in[8];
    const float* ws    = (const float*)d_in[9];
    const float* wt    = (const float*)d_in[10];
    const float* Wnode = (const float*)d_in[11];
    const float* bnode = (const float*)d_in[12];
    float* out = (float*)d_out;
    int E = in_sizes[2];
    if (E > NE) E = NE;

    zero_deg_kernel<<<(NN + 255) / 256, 256>>>();

    dim3 gg((NN + 63) / 64, 2);
    gemm_in_tc_kernel<<<gg, 256>>>(fsrc, ftgt, Wsrc, bsrc, Wtgt, btgt);

    int eg = (E + 255) / 256;
    hist_kernel<<<eg, 256>>>(erow, ecol, E);
    dim3 sgr(NBLK, 2);
    scan_partial_kernel<<<sgr, SCB>>>();
    scan_final_kernel<<<sgr, SCB>>>(E);
    scatter_kernel<<<eg, 256>>>(erow, ecol, ew, E);

    dim3 sg((NN * 32 + 255) / 256, 2);  // one warp per row, y = path
    spmm_kernel<<<sg, 256>>>(1);  // x  -> h1
    spmm_kernel<<<sg, 256>>>(2);  // h1 -> h2
    spmm_kernel<<<sg, 256>>>(3);  // h2 -> h3

    gemm_out_tc_kernel<<<(NN + 63) / 64, 128>>>(Wnode, bnode, ws, wt, out);
}